// round 11
// baseline (speedup 1.0000x reference)
#include <cuda_runtime.h>
#include <cstdint>

typedef unsigned long long ull;

// ---------- packed f32x2 helpers (Blackwell sm_100+) ----------
__device__ __forceinline__ ull pack2(float a, float b) {
    ull r;
    asm("mov.b64 %0, {%1, %2};" : "=l"(r) : "r"(__float_as_uint(a)), "r"(__float_as_uint(b)));
    return r;
}
__device__ __forceinline__ void unpack2(ull v, float& a, float& b) {
    unsigned ua, ub;
    asm("mov.b64 {%0, %1}, %2;" : "=r"(ua), "=r"(ub) : "l"(v));
    a = __uint_as_float(ua);
    b = __uint_as_float(ub);
}
__device__ __forceinline__ ull fma2(ull a, ull b, ull c) {
    ull d;
    asm("fma.rn.f32x2 %0, %1, %2, %3;" : "=l"(d) : "l"(a), "l"(b), "l"(c));
    return d;
}
__device__ __forceinline__ ull mul2(ull a, ull b) {
    ull d;
    asm("mul.rn.f32x2 %0, %1, %2;" : "=l"(d) : "l"(a), "l"(b));
    return d;
}

// packed constants: same fp32 in both halves
#define PKC(x) ((((ull)(x)) << 32) | (ull)(x))
static __device__ __forceinline__ ull k5()  { return PKC(0x40A00000u); }  // 5.0f
static __device__ __forceinline__ ull k10() { return PKC(0x41200000u); }  // 10.0f
static __device__ __forceinline__ ull k2()  { return PKC(0x40000000u); }  // 2.0f
static __device__ __forceinline__ ull km1() { return PKC(0xBF800000u); }  // -1.0f

// Degree-5 Bernstein basis for two points at once.
// B_i(s) = C(5,i) s^i (1-s)^(5-i)
__device__ __forceinline__ void bern6(float sa, float sb, ull B[6]) {
    ull s  = pack2(sa, sb);
    ull u  = pack2(1.0f - sa, 1.0f - sb);
    ull s2 = mul2(s, s);
    ull s3 = mul2(s2, s);
    ull s4 = mul2(s2, s2);
    ull s5 = mul2(s4, s);
    ull u2 = mul2(u, u);
    ull u3 = mul2(u2, u);
    ull u4 = mul2(u2, u2);
    ull u5 = mul2(u4, u);
    B[0] = u5;
    B[1] = mul2(k5(),  mul2(s,  u4));
    B[2] = mul2(k10(), mul2(s2, u3));
    B[3] = mul2(k10(), mul2(s3, u2));
    B[4] = mul2(k5(),  mul2(s4, u));
    B[5] = s5;
}

// p layout in shared: [c][i][j][k] as (p,p) doubled 64-bit values, 648 entries.
// Row base (c,i,j) is a multiple of 6 entries -> byte offset multiple of 48 -> 16B aligned,
// so ulonglong2 (LDS.128) fetches of k-pairs are legal.
__global__ void __launch_bounds__(256) ffd_kernel(
    const float* __restrict__ verts,   // [N,3]
    const float* __restrict__ p,       // [3,6,6,6] = 648
    float* __restrict__ out,           // [1,N,3]
    int N)
{
    __shared__ __align__(16) ull shp[648];
    for (int t = threadIdx.x; t < 648; t += blockDim.x) {
        float v = p[t];
        shp[t] = pack2(v, v);
    }
    __syncthreads();

    int pair = blockIdx.x * blockDim.x + threadIdx.x;
    int ia = 2 * pair;
    if (ia >= N) return;
    bool haveB = (ia + 1) < N;

    // load coords for points ia, ia+1
    float xa, ya, za, xb, yb, zb;
    if (haveB) {
        const float2* vp = reinterpret_cast<const float2*>(verts + 6 * (size_t)pair);
        float2 v0 = vp[0], v1 = vp[1], v2 = vp[2];
        xa = v0.x; ya = v0.y; za = v1.x;
        xb = v1.y; yb = v2.x; zb = v2.y;
    } else {
        const float* vv = verts + 3 * (size_t)ia;
        xa = vv[0]; ya = vv[1]; za = vv[2];
        xb = xa; yb = ya; zb = za;
    }

    // s = (v + 1) * 0.5
    float sxa = fmaf(xa, 0.5f, 0.5f), sxb = fmaf(xb, 0.5f, 0.5f);
    float sya = fmaf(ya, 0.5f, 0.5f), syb = fmaf(yb, 0.5f, 0.5f);
    float sza = fmaf(za, 0.5f, 0.5f), szb = fmaf(zb, 0.5f, 0.5f);

    ull Bx[6], By[6], Bz[6];
    bern6(sxa, sxb, Bx);
    bern6(sya, syb, By);
    bern6(sza, szb, Bz);

    float qa[3], qb[3];

    #pragma unroll
    for (int c = 0; c < 3; c++) {
        ull qc = 0ull;
        #pragma unroll
        for (int i = 0; i < 6; i++) {
            ull ti = 0ull;
            #pragma unroll
            for (int j = 0; j < 6; j++) {
                const ulonglong2* row =
                    reinterpret_cast<const ulonglong2*>(&shp[(c * 36 + i * 6 + j) * 6]);
                ulonglong2 r0 = row[0];
                ulonglong2 r1 = row[1];
                ulonglong2 r2 = row[2];
                ull u = mul2(Bz[0], r0.x);
                u = fma2(Bz[1], r0.y, u);
                u = fma2(Bz[2], r1.x, u);
                u = fma2(Bz[3], r1.y, u);
                u = fma2(Bz[4], r2.x, u);
                u = fma2(Bz[5], r2.y, u);
                if (j == 0) ti = mul2(By[0], u);
                else        ti = fma2(By[j], u, ti);
            }
            if (i == 0) qc = mul2(Bx[0], ti);
            else        qc = fma2(Bx[i], ti, qc);
        }
        // q = 2*q - 1
        qc = fma2(k2(), qc, km1());
        unpack2(qc, qa[c], qb[c]);
    }

    if (haveB) {
        float2* op = reinterpret_cast<float2*>(out + 6 * (size_t)pair);
        op[0] = make_float2(qa[0], qa[1]);
        op[1] = make_float2(qa[2], qb[0]);
        op[2] = make_float2(qb[1], qb[2]);
    } else {
        float* op = out + 3 * (size_t)ia;
        op[0] = qa[0]; op[1] = qa[1]; op[2] = qa[2];
    }
}

extern "C" void kernel_launch(void* const* d_in, const int* in_sizes, int n_in,
                              void* d_out, int out_size) {
    // identify inputs by size: p has 3*6*6*6 = 648 elements, vertices has N*3
    const float* a = (const float*)d_in[0];
    const float* b = (const float*)d_in[1];
    const float* verts;
    const float* p;
    int nv;
    if (in_sizes[0] >= in_sizes[1]) {
        verts = a; p = b; nv = in_sizes[0];
    } else {
        verts = b; p = a; nv = in_sizes[1];
    }
    int N = nv / 3;
    int pairs = (N + 1) / 2;
    int threads = 256;
    int blocks = (pairs + threads - 1) / threads;
    ffd_kernel<<<blocks, threads>>>(verts, p, (float*)d_out, N);
}

// round 13
// speedup vs baseline: 1.1295x; 1.1295x over previous
#include <cuda_runtime.h>
#include <cstdint>

typedef unsigned long long ull;

// ---------- packed f32x2 helpers (Blackwell sm_100+) ----------
__device__ __forceinline__ ull pack2(float a, float b) {
    ull r;
    asm("mov.b64 %0, {%1, %2};" : "=l"(r) : "r"(__float_as_uint(a)), "r"(__float_as_uint(b)));
    return r;
}
__device__ __forceinline__ void unpack2(ull v, float& a, float& b) {
    unsigned ua, ub;
    asm("mov.b64 {%0, %1}, %2;" : "=r"(ua), "=r"(ub) : "l"(v));
    a = __uint_as_float(ua);
    b = __uint_as_float(ub);
}
__device__ __forceinline__ ull fma2(ull a, ull b, ull c) {
    ull d;
    asm("fma.rn.f32x2 %0, %1, %2, %3;" : "=l"(d) : "l"(a), "l"(b), "l"(c));
    return d;
}
__device__ __forceinline__ ull mul2(ull a, ull b) {
    ull d;
    asm("mul.rn.f32x2 %0, %1, %2;" : "=l"(d) : "l"(a), "l"(b));
    return d;
}

// packed constants: same fp32 in both halves
#define PKC(x) ((((ull)(x)) << 32) | (ull)(x))
static __device__ __forceinline__ ull k5()  { return PKC(0x40A00000u); }  // 5.0f
static __device__ __forceinline__ ull k10() { return PKC(0x41200000u); }  // 10.0f
static __device__ __forceinline__ ull k2()  { return PKC(0x40000000u); }  // 2.0f
static __device__ __forceinline__ ull km1() { return PKC(0xBF800000u); }  // -1.0f

// Degree-5 Bernstein basis for two points at once.
// B_i(s) = C(5,i) s^i (1-s)^(5-i)
__device__ __forceinline__ void bern6(float sa, float sb, ull B[6]) {
    ull s  = pack2(sa, sb);
    ull u  = pack2(1.0f - sa, 1.0f - sb);
    ull s2 = mul2(s, s);
    ull s3 = mul2(s2, s);
    ull s4 = mul2(s2, s2);
    ull s5 = mul2(s4, s);
    ull u2 = mul2(u, u);
    ull u3 = mul2(u2, u);
    ull u4 = mul2(u2, u2);
    ull u5 = mul2(u4, u);
    B[0] = u5;
    B[1] = mul2(k5(),  mul2(s,  u4));
    B[2] = mul2(k10(), mul2(s2, u3));
    B[3] = mul2(k10(), mul2(s3, u2));
    B[4] = mul2(k5(),  mul2(s4, u));
    B[5] = s5;
}

// p in shared: [c][i][j][k] as (p,p) doubled 64-bit values, 648 entries.
// Each (c,i,j) row = 6 doubled entries = 48 bytes, 16B aligned -> 3x LDS.128.
// 4 points per thread: two packed pairs (A = pts 0,1 ; B = pts 2,3) share
// every row fetch, halving LDS bytes/point vs the 2-point kernel.
__global__ void __launch_bounds__(256) ffd_kernel(
    const float* __restrict__ verts,   // [N,3]
    const float* __restrict__ p,       // [3,6,6,6] = 648
    float* __restrict__ out,           // [1,N,3]
    int N)
{
    __shared__ __align__(16) ull shp[648];
    for (int t = threadIdx.x; t < 648; t += blockDim.x) {
        float v = p[t];
        shp[t] = pack2(v, v);
    }
    __syncthreads();

    long long gid  = (long long)blockIdx.x * blockDim.x + threadIdx.x;
    long long base = 4 * gid;
    if (base >= N) return;
    bool fast = (base + 3) < N;

    // coords for points base .. base+3
    float x[4], y[4], z[4];
    if (fast) {
        const float4* vp = reinterpret_cast<const float4*>(verts + 3 * base);
        float4 a = vp[0], b = vp[1], c = vp[2];
        x[0]=a.x; y[0]=a.y; z[0]=a.z;
        x[1]=a.w; y[1]=b.x; z[1]=b.y;
        x[2]=b.z; y[2]=b.w; z[2]=c.x;
        x[3]=c.y; y[3]=c.z; z[3]=c.w;
    } else {
        #pragma unroll
        for (int t = 0; t < 4; t++) {
            long long idx = base + t;
            if (idx > (long long)N - 1) idx = (long long)N - 1;
            const float* vv = verts + 3 * idx;
            x[t] = vv[0]; y[t] = vv[1]; z[t] = vv[2];
        }
    }

    // s = (v + 1) * 0.5
    float sx[4], sy[4], sz[4];
    #pragma unroll
    for (int t = 0; t < 4; t++) {
        sx[t] = fmaf(x[t], 0.5f, 0.5f);
        sy[t] = fmaf(y[t], 0.5f, 0.5f);
        sz[t] = fmaf(z[t], 0.5f, 0.5f);
    }

    ull BxA[6], ByA[6], BzA[6];   // pair A = points 0,1
    ull BxB[6], ByB[6], BzB[6];   // pair B = points 2,3
    bern6(sx[0], sx[1], BxA);
    bern6(sy[0], sy[1], ByA);
    bern6(sz[0], sz[1], BzA);
    bern6(sx[2], sx[3], BxB);
    bern6(sy[2], sy[3], ByB);
    bern6(sz[2], sz[3], BzB);

    float q[4][3];

    #pragma unroll
    for (int c = 0; c < 3; c++) {
        ull qcA = 0ull, qcB = 0ull;
        #pragma unroll
        for (int i = 0; i < 6; i++) {
            ull tiA = 0ull, tiB = 0ull;
            #pragma unroll
            for (int j = 0; j < 6; j++) {
                const ulonglong2* row =
                    reinterpret_cast<const ulonglong2*>(&shp[(c * 36 + i * 6 + j) * 6]);
                ulonglong2 r0 = row[0];
                ulonglong2 r1 = row[1];
                ulonglong2 r2 = row[2];

                ull uA = mul2(BzA[0], r0.x);
                ull uB = mul2(BzB[0], r0.x);
                uA = fma2(BzA[1], r0.y, uA);
                uB = fma2(BzB[1], r0.y, uB);
                uA = fma2(BzA[2], r1.x, uA);
                uB = fma2(BzB[2], r1.x, uB);
                uA = fma2(BzA[3], r1.y, uA);
                uB = fma2(BzB[3], r1.y, uB);
                uA = fma2(BzA[4], r2.x, uA);
                uB = fma2(BzB[4], r2.x, uB);
                uA = fma2(BzA[5], r2.y, uA);
                uB = fma2(BzB[5], r2.y, uB);

                if (j == 0) { tiA = mul2(ByA[0], uA); tiB = mul2(ByB[0], uB); }
                else        { tiA = fma2(ByA[j], uA, tiA); tiB = fma2(ByB[j], uB, tiB); }
            }
            if (i == 0) { qcA = mul2(BxA[0], tiA); qcB = mul2(BxB[0], tiB); }
            else        { qcA = fma2(BxA[i], tiA, qcA); qcB = fma2(BxB[i], tiB, qcB); }
        }
        // q = 2*q - 1
        qcA = fma2(k2(), qcA, km1());
        qcB = fma2(k2(), qcB, km1());
        unpack2(qcA, q[0][c], q[1][c]);
        unpack2(qcB, q[2][c], q[3][c]);
    }

    if (fast) {
        float4* op = reinterpret_cast<float4*>(out + 3 * base);
        op[0] = make_float4(q[0][0], q[0][1], q[0][2], q[1][0]);
        op[1] = make_float4(q[1][1], q[1][2], q[2][0], q[2][1]);
        op[2] = make_float4(q[2][2], q[3][0], q[3][1], q[3][2]);
    } else {
        #pragma unroll
        for (int t = 0; t < 4; t++) {
            long long idx = base + t;
            if (idx < N) {
                float* op = out + 3 * idx;
                op[0] = q[t][0]; op[1] = q[t][1]; op[2] = q[t][2];
            }
        }
    }
}

extern "C" void kernel_launch(void* const* d_in, const int* in_sizes, int n_in,
                              void* d_out, int out_size) {
    // identify inputs by size: p has 3*6*6*6 = 648 elements, vertices has N*3
    const float* a = (const float*)d_in[0];
    const float* b = (const float*)d_in[1];
    const float* verts;
    const float* p;
    int nv;
    if (in_sizes[0] >= in_sizes[1]) {
        verts = a; p = b; nv = in_sizes[0];
    } else {
        verts = b; p = a; nv = in_sizes[1];
    }
    int N = nv / 3;
    int groups = (N + 3) / 4;
    int threads = 256;
    int blocks = (groups + threads - 1) / threads;
    ffd_kernel<<<blocks, threads>>>(verts, p, (float*)d_out, N);
}

// round 16
// speedup vs baseline: 1.2250x; 1.0846x over previous
#include <cuda_runtime.h>
#include <cstdint>

typedef unsigned long long ull;

// ---------- packed f32x2 helpers (Blackwell sm_100+) ----------
__device__ __forceinline__ ull pack2(float a, float b) {
    ull r;
    asm("mov.b64 %0, {%1, %2};" : "=l"(r) : "r"(__float_as_uint(a)), "r"(__float_as_uint(b)));
    return r;
}
__device__ __forceinline__ void unpack2(ull v, float& a, float& b) {
    unsigned ua, ub;
    asm("mov.b64 {%0, %1}, %2;" : "=r"(ua), "=r"(ub) : "l"(v));
    a = __uint_as_float(ua);
    b = __uint_as_float(ub);
}
__device__ __forceinline__ ull fma2(ull a, ull b, ull c) {
    ull d;
    asm("fma.rn.f32x2 %0, %1, %2, %3;" : "=l"(d) : "l"(a), "l"(b), "l"(c));
    return d;
}
__device__ __forceinline__ ull mul2(ull a, ull b) {
    ull d;
    asm("mul.rn.f32x2 %0, %1, %2;" : "=l"(d) : "l"(a), "l"(b));
    return d;
}

// packed constants: same fp32 in both halves
#define PKC(x) ((((ull)(x)) << 32) | (ull)(x))
static __device__ __forceinline__ ull k5()  { return PKC(0x40A00000u); }  // 5.0f
static __device__ __forceinline__ ull k10() { return PKC(0x41200000u); }  // 10.0f
static __device__ __forceinline__ ull k2()  { return PKC(0x40000000u); }  // 2.0f
static __device__ __forceinline__ ull km1() { return PKC(0xBF800000u); }  // -1.0f

// Doubled (p,p) lattice: staged on device by prep kernel, then copied into
// __constant__ so the main kernel reads it through the constant/uniform port
// (LDC) instead of the LSU — frees L1/shared entirely for vertex I/O.
__device__   __align__(16) ull g_stage[648];
__constant__ __align__(16) ull c_p2[648];

__global__ void prep_kernel(const float* __restrict__ p) {
    int t = blockIdx.x * blockDim.x + threadIdx.x;
    if (t < 648) {
        float v = p[t];
        g_stage[t] = pack2(v, v);
    }
}

// Degree-5 Bernstein basis for two points at once.
// B_i(s) = C(5,i) s^i (1-s)^(5-i)
__device__ __forceinline__ void bern6(float sa, float sb, ull B[6]) {
    ull s  = pack2(sa, sb);
    ull u  = pack2(1.0f - sa, 1.0f - sb);
    ull s2 = mul2(s, s);
    ull s3 = mul2(s2, s);
    ull s4 = mul2(s2, s2);
    ull s5 = mul2(s4, s);
    ull u2 = mul2(u, u);
    ull u3 = mul2(u2, u);
    ull u4 = mul2(u2, u2);
    ull u5 = mul2(u4, u);
    B[0] = u5;
    B[1] = mul2(k5(),  mul2(s,  u4));
    B[2] = mul2(k10(), mul2(s2, u3));
    B[3] = mul2(k10(), mul2(s3, u2));
    B[4] = mul2(k5(),  mul2(s4, u));
    B[5] = s5;
}

// 4 points per thread: two packed pairs (A = pts 0,1 ; B = pts 2,3) share
// every constant row fetch. All lattice reads go through the constant port.
__global__ void __launch_bounds__(256) ffd_kernel(
    const float* __restrict__ verts,   // [N,3]
    float* __restrict__ out,           // [1,N,3]
    int N)
{
    long long gid  = (long long)blockIdx.x * blockDim.x + threadIdx.x;
    long long base = 4 * gid;
    if (base >= N) return;
    bool fast = (base + 3) < N;

    // coords for points base .. base+3
    float x[4], y[4], z[4];
    if (fast) {
        const float4* vp = reinterpret_cast<const float4*>(verts + 3 * base);
        float4 a = vp[0], b = vp[1], c = vp[2];
        x[0]=a.x; y[0]=a.y; z[0]=a.z;
        x[1]=a.w; y[1]=b.x; z[1]=b.y;
        x[2]=b.z; y[2]=b.w; z[2]=c.x;
        x[3]=c.y; y[3]=c.z; z[3]=c.w;
    } else {
        #pragma unroll
        for (int t = 0; t < 4; t++) {
            long long idx = base + t;
            if (idx > (long long)N - 1) idx = (long long)N - 1;
            const float* vv = verts + 3 * idx;
            x[t] = vv[0]; y[t] = vv[1]; z[t] = vv[2];
        }
    }

    // s = (v + 1) * 0.5
    float sx[4], sy[4], sz[4];
    #pragma unroll
    for (int t = 0; t < 4; t++) {
        sx[t] = fmaf(x[t], 0.5f, 0.5f);
        sy[t] = fmaf(y[t], 0.5f, 0.5f);
        sz[t] = fmaf(z[t], 0.5f, 0.5f);
    }

    ull BxA[6], ByA[6], BzA[6];   // pair A = points 0,1
    ull BxB[6], ByB[6], BzB[6];   // pair B = points 2,3
    bern6(sx[0], sx[1], BxA);
    bern6(sy[0], sy[1], ByA);
    bern6(sz[0], sz[1], BzA);
    bern6(sx[2], sx[3], BxB);
    bern6(sy[2], sy[3], ByB);
    bern6(sz[2], sz[3], BzB);

    float q[4][3];

    #pragma unroll
    for (int c = 0; c < 3; c++) {
        ull qcA = 0ull, qcB = 0ull;
        #pragma unroll
        for (int i = 0; i < 6; i++) {
            ull tiA = 0ull, tiB = 0ull;
            #pragma unroll
            for (int j = 0; j < 6; j++) {
                const ulonglong2* row =
                    reinterpret_cast<const ulonglong2*>(&c_p2[(c * 36 + i * 6 + j) * 6]);
                ulonglong2 r0 = row[0];
                ulonglong2 r1 = row[1];
                ulonglong2 r2 = row[2];

                ull uA = mul2(BzA[0], r0.x);
                ull uB = mul2(BzB[0], r0.x);
                uA = fma2(BzA[1], r0.y, uA);
                uB = fma2(BzB[1], r0.y, uB);
                uA = fma2(BzA[2], r1.x, uA);
                uB = fma2(BzB[2], r1.x, uB);
                uA = fma2(BzA[3], r1.y, uA);
                uB = fma2(BzB[3], r1.y, uB);
                uA = fma2(BzA[4], r2.x, uA);
                uB = fma2(BzB[4], r2.x, uB);
                uA = fma2(BzA[5], r2.y, uA);
                uB = fma2(BzB[5], r2.y, uB);

                if (j == 0) { tiA = mul2(ByA[0], uA); tiB = mul2(ByB[0], uB); }
                else        { tiA = fma2(ByA[j], uA, tiA); tiB = fma2(ByB[j], uB, tiB); }
            }
            if (i == 0) { qcA = mul2(BxA[0], tiA); qcB = mul2(BxB[0], tiB); }
            else        { qcA = fma2(BxA[i], tiA, qcA); qcB = fma2(BxB[i], tiB, qcB); }
        }
        // q = 2*q - 1
        qcA = fma2(k2(), qcA, km1());
        qcB = fma2(k2(), qcB, km1());
        unpack2(qcA, q[0][c], q[1][c]);
        unpack2(qcB, q[2][c], q[3][c]);
    }

    if (fast) {
        float4* op = reinterpret_cast<float4*>(out + 3 * base);
        op[0] = make_float4(q[0][0], q[0][1], q[0][2], q[1][0]);
        op[1] = make_float4(q[1][1], q[1][2], q[2][0], q[2][1]);
        op[2] = make_float4(q[2][2], q[3][0], q[3][1], q[3][2]);
    } else {
        #pragma unroll
        for (int t = 0; t < 4; t++) {
            long long idx = base + t;
            if (idx < N) {
                float* op = out + 3 * idx;
                op[0] = q[t][0]; op[1] = q[t][1]; op[2] = q[t][2];
            }
        }
    }
}

extern "C" void kernel_launch(void* const* d_in, const int* in_sizes, int n_in,
                              void* d_out, int out_size) {
    // identify inputs by size: p has 3*6*6*6 = 648 elements, vertices has N*3
    const float* a = (const float*)d_in[0];
    const float* b = (const float*)d_in[1];
    const float* verts;
    const float* p;
    int nv;
    if (in_sizes[0] >= in_sizes[1]) {
        verts = a; p = b; nv = in_sizes[0];
    } else {
        verts = b; p = a; nv = in_sizes[1];
    }
    int N = nv / 3;

    // 1) double p into staging (device global), 2) copy into __constant__
    //    (device-to-device memcpy node — graph-capturable), 3) main kernel.
    prep_kernel<<<3, 256>>>(p);
    void* stage_ptr = nullptr;
    cudaGetSymbolAddress(&stage_ptr, g_stage);
    cudaMemcpyToSymbolAsync(c_p2, stage_ptr, sizeof(ull) * 648, 0,
                            cudaMemcpyDeviceToDevice, 0);

    int groups = (N + 3) / 4;
    int threads = 256;
    int blocks = (groups + threads - 1) / threads;
    ffd_kernel<<<blocks, threads>>>(verts, (float*)d_out, N);
}